// round 2
// baseline (speedup 1.0000x reference)
#include <cuda_runtime.h>
#include <math.h>

#define B 4
#define S 2048
#define D 1024
#define H 16
#define DH 64
#define M (B * S)          // 8192
#define EPS 1e-5f

// ---------------- scratch (no allocations allowed) ----------------
__device__ float g_q[(size_t)B * H * S * DH];     // [B,H,S,DH]
__device__ float g_k[(size_t)B * H * S * DH];
__device__ float g_v[(size_t)B * H * S * DH];
__device__ float g_ctx[(size_t)B * S * D];        // concat heads [B,S,D]
__device__ float g_tmp[(size_t)B * S * D];        // proj + residual, pre-LN

// ============================================================================
// Kernel 1: QKV projection.  q[b,h,s,k] = sum_d x[b,s,d] * Wq[h,d,k]
// grid (M/128, H, 3), block 256.  Tile 128x64, K-tile 16, 8x4 per thread.
// ============================================================================
__global__ __launch_bounds__(256) void qkv_kernel(
    const float* __restrict__ x,
    const float* __restrict__ Wq,
    const float* __restrict__ Wk,
    const float* __restrict__ Wv)
{
    __shared__ __align__(16) float Xs[16][132];   // [kk][m], padded
    __shared__ __align__(16) float Ws[16][64];    // [kk][n]

    const int m0 = blockIdx.x * 128;
    const int h  = blockIdx.y;
    const float* W = (blockIdx.z == 0 ? Wq : (blockIdx.z == 1 ? Wk : Wv))
                     + (size_t)h * D * DH;
    float* outp = (blockIdx.z == 0 ? g_q : (blockIdx.z == 1 ? g_k : g_v));

    const int tid = threadIdx.x;
    const int tx = tid & 15, ty = tid >> 4;

    float acc[8][4];
    #pragma unroll
    for (int i = 0; i < 8; i++)
        #pragma unroll
        for (int j = 0; j < 4; j++) acc[i][j] = 0.f;

    for (int k0 = 0; k0 < D; k0 += 16) {
        #pragma unroll
        for (int i = 0; i < 8; i++) {                 // X tile 128x16
            int idx = tid + 256 * i;
            int r = idx >> 4, c = idx & 15;
            Xs[c][r] = x[(size_t)(m0 + r) * D + (k0 + c)];
        }
        #pragma unroll
        for (int i = 0; i < 4; i++) {                 // W tile 16x64
            int idx = tid + 256 * i;
            int r = idx >> 6, c = idx & 63;
            Ws[r][c] = W[(size_t)(k0 + r) * DH + c];
        }
        __syncthreads();
        #pragma unroll
        for (int kk = 0; kk < 16; kk++) {
            float4 bv = *(const float4*)&Ws[kk][tx * 4];
            #pragma unroll
            for (int i = 0; i < 8; i++) {
                float a = Xs[kk][ty * 8 + i];
                acc[i][0] += a * bv.x; acc[i][1] += a * bv.y;
                acc[i][2] += a * bv.z; acc[i][3] += a * bv.w;
            }
        }
        __syncthreads();
    }
    #pragma unroll
    for (int i = 0; i < 8; i++) {
        int m = m0 + ty * 8 + i;
        int bb = m >> 11;              // / S
        int s  = m & (S - 1);
        float4 o4 = make_float4(acc[i][0], acc[i][1], acc[i][2], acc[i][3]);
        *(float4*)&outp[(((size_t)bb * H + h) * S + s) * DH + tx * 4] = o4;
    }
}

// ============================================================================
// Kernel 2: flash attention.  grid (S/128, B*H), block 256 (16x16).
// 128-query tile, 64-key tiles, online softmax, P through SMEM for PV.
// ============================================================================
#define KST 68   // padded stride for transposed K tile (conflict-free f4 reads)

__global__ __launch_bounds__(256, 2) void attn_kernel()
{
    extern __shared__ __align__(16) float smem[];
    float* Qs  = smem;                       // [128][64]
    float* KsT = smem + 128 * 64;            // [64][KST]  (dh-major)
    float* Vs  = KsT + 64 * KST;             // [64][64]
    float* Ps  = Vs + 64 * 64;               // [128][64]

    const int bh = blockIdx.y;
    const int q0 = blockIdx.x * 128;
    const float* Qg = g_q + (size_t)bh * S * DH;
    const float* Kg = g_k + (size_t)bh * S * DH;
    const float* Vg = g_v + (size_t)bh * S * DH;

    const int tid = threadIdx.x;
    const int tx = tid & 15, ty = tid >> 4;

    // load Q tile, pre-scaled by 1/sqrt(DH)
    #pragma unroll
    for (int i = 0; i < 8; i++) {
        int idx = tid + 256 * i;             // float4 index, 0..2047
        int r = idx >> 4, c = (idx & 15) * 4;
        float4 v = *(const float4*)&Qg[(size_t)(q0 + r) * DH + c];
        v.x *= 0.125f; v.y *= 0.125f; v.z *= 0.125f; v.w *= 0.125f;
        *(float4*)&Qs[r * 64 + c] = v;
    }

    float m_run[8], l_run[8], acc[8][4];
    #pragma unroll
    for (int i = 0; i < 8; i++) {
        m_run[i] = -1e30f; l_run[i] = 0.f;
        #pragma unroll
        for (int j = 0; j < 4; j++) acc[i][j] = 0.f;
    }

    for (int kt = 0; kt < S; kt += 64) {
        // load K (transposed) and V tiles
        #pragma unroll
        for (int i = 0; i < 16; i++) {
            int idx = tid + 256 * i;         // 0..4095
            int r = idx >> 6, c = idx & 63;
            KsT[c * KST + r] = Kg[(size_t)(kt + r) * DH + c];
        }
        #pragma unroll
        for (int i = 0; i < 4; i++) {
            int idx = tid + 256 * i;         // float4 index, 0..1023
            int r = idx >> 4, c = (idx & 15) * 4;
            *(float4*)&Vs[r * 64 + c] = *(const float4*)&Vg[(size_t)(kt + r) * DH + c];
        }
        __syncthreads();

        // scores: s = (Q*0.125) @ K^T   (8x4 per thread)
        float sc[8][4];
        #pragma unroll
        for (int i = 0; i < 8; i++)
            #pragma unroll
            for (int j = 0; j < 4; j++) sc[i][j] = 0.f;

        #pragma unroll 8
        for (int kk = 0; kk < 64; kk++) {
            float4 bv = *(const float4*)&KsT[kk * KST + tx * 4];
            #pragma unroll
            for (int i = 0; i < 8; i++) {
                float a = Qs[(ty * 8 + i) * 64 + kk];
                sc[i][0] += a * bv.x; sc[i][1] += a * bv.y;
                sc[i][2] += a * bv.z; sc[i][3] += a * bv.w;
            }
        }

        // online softmax update + write P tile
        #pragma unroll
        for (int i = 0; i < 8; i++) {
            float tm = fmaxf(fmaxf(sc[i][0], sc[i][1]), fmaxf(sc[i][2], sc[i][3]));
            tm = fmaxf(tm, __shfl_xor_sync(0xffffffffu, tm, 8));
            tm = fmaxf(tm, __shfl_xor_sync(0xffffffffu, tm, 4));
            tm = fmaxf(tm, __shfl_xor_sync(0xffffffffu, tm, 2));
            tm = fmaxf(tm, __shfl_xor_sync(0xffffffffu, tm, 1));
            float mn = fmaxf(m_run[i], tm);
            float alpha = __expf(m_run[i] - mn);
            m_run[i] = mn;
            float p0 = __expf(sc[i][0] - mn);
            float p1 = __expf(sc[i][1] - mn);
            float p2 = __expf(sc[i][2] - mn);
            float p3 = __expf(sc[i][3] - mn);
            float rs = p0 + p1 + p2 + p3;
            rs += __shfl_xor_sync(0xffffffffu, rs, 8);
            rs += __shfl_xor_sync(0xffffffffu, rs, 4);
            rs += __shfl_xor_sync(0xffffffffu, rs, 2);
            rs += __shfl_xor_sync(0xffffffffu, rs, 1);
            l_run[i] = l_run[i] * alpha + rs;
            acc[i][0] *= alpha; acc[i][1] *= alpha;
            acc[i][2] *= alpha; acc[i][3] *= alpha;
            *(float4*)&Ps[(ty * 8 + i) * 64 + tx * 4] = make_float4(p0, p1, p2, p3);
        }
        __syncthreads();

        // PV: acc += P @ V
        #pragma unroll 8
        for (int ss = 0; ss < 64; ss++) {
            float4 vv = *(const float4*)&Vs[ss * 64 + tx * 4];
            #pragma unroll
            for (int i = 0; i < 8; i++) {
                float p = Ps[(ty * 8 + i) * 64 + ss];
                acc[i][0] += p * vv.x; acc[i][1] += p * vv.y;
                acc[i][2] += p * vv.z; acc[i][3] += p * vv.w;
            }
        }
        __syncthreads();
    }

    // epilogue: normalize and write concat layout [B,S,D]
    const int bb = bh >> 4, h = bh & 15;
    #pragma unroll
    for (int i = 0; i < 8; i++) {
        float inv = 1.f / l_run[i];
        int qrow = q0 + ty * 8 + i;
        float4 o = make_float4(acc[i][0] * inv, acc[i][1] * inv,
                               acc[i][2] * inv, acc[i][3] * inv);
        *(float4*)&g_ctx[((size_t)bb * S + qrow) * D + h * DH + tx * 4] = o;
    }
}

// ============================================================================
// Kernel 3: output projection + bias + residual.  grid (M/128, D/64), block 256.
// g_tmp = g_ctx @ Wo + bo + x
// ============================================================================
__global__ __launch_bounds__(256) void proj_kernel(
    const float* __restrict__ x,
    const float* __restrict__ Wo,
    const float* __restrict__ bo)
{
    __shared__ __align__(16) float Xs[16][132];
    __shared__ __align__(16) float Ws[16][64];

    const int m0 = blockIdx.x * 128;
    const int n0 = blockIdx.y * 64;
    const int tid = threadIdx.x;
    const int tx = tid & 15, ty = tid >> 4;

    float acc[8][4];
    #pragma unroll
    for (int i = 0; i < 8; i++)
        #pragma unroll
        for (int j = 0; j < 4; j++) acc[i][j] = 0.f;

    for (int k0 = 0; k0 < D; k0 += 16) {
        #pragma unroll
        for (int i = 0; i < 8; i++) {
            int idx = tid + 256 * i;
            int r = idx >> 4, c = idx & 15;
            Xs[c][r] = g_ctx[(size_t)(m0 + r) * D + (k0 + c)];
        }
        #pragma unroll
        for (int i = 0; i < 4; i++) {
            int idx = tid + 256 * i;
            int r = idx >> 6, c = idx & 63;
            Ws[r][c] = Wo[(size_t)(k0 + r) * D + (n0 + c)];
        }
        __syncthreads();
        #pragma unroll
        for (int kk = 0; kk < 16; kk++) {
            float4 bv = *(const float4*)&Ws[kk][tx * 4];
            #pragma unroll
            for (int i = 0; i < 8; i++) {
                float a = Xs[kk][ty * 8 + i];
                acc[i][0] += a * bv.x; acc[i][1] += a * bv.y;
                acc[i][2] += a * bv.z; acc[i][3] += a * bv.w;
            }
        }
        __syncthreads();
    }
    float4 bv = *(const float4*)&bo[n0 + tx * 4];
    #pragma unroll
    for (int i = 0; i < 8; i++) {
        int m = m0 + ty * 8 + i;
        float4 xv = *(const float4*)&x[(size_t)m * D + n0 + tx * 4];
        float4 o4 = make_float4(acc[i][0] + bv.x + xv.x,
                                acc[i][1] + bv.y + xv.y,
                                acc[i][2] + bv.z + xv.z,
                                acc[i][3] + bv.w + xv.w);
        *(float4*)&g_tmp[(size_t)m * D + n0 + tx * 4] = o4;
    }
}

// ============================================================================
// Kernel 4: LayerNorm per row.  grid M, block 256 (4 floats / thread).
// ============================================================================
__global__ __launch_bounds__(256) void ln_kernel(
    const float* __restrict__ gamma,
    const float* __restrict__ beta,
    float* __restrict__ out)
{
    const int row = blockIdx.x;
    const int t = threadIdx.x;
    const float4* src = (const float4*)(g_tmp + (size_t)row * D);
    float4 v = src[t];

    float s = v.x + v.y + v.z + v.w;
    float q = v.x * v.x + v.y * v.y + v.z * v.z + v.w * v.w;
    #pragma unroll
    for (int o = 16; o > 0; o >>= 1) {
        s += __shfl_xor_sync(0xffffffffu, s, o);
        q += __shfl_xor_sync(0xffffffffu, q, o);
    }
    __shared__ float sh[16];
    int w = t >> 5, lane = t & 31;
    if (lane == 0) { sh[w] = s; sh[8 + w] = q; }
    __syncthreads();
    if (t < 32) {
        s = (lane < 8) ? sh[lane] : 0.f;
        q = (lane < 8) ? sh[8 + lane] : 0.f;
        #pragma unroll
        for (int o = 4; o > 0; o >>= 1) {
            s += __shfl_xor_sync(0xffffffffu, s, o);
            q += __shfl_xor_sync(0xffffffffu, q, o);
        }
        if (lane == 0) { sh[0] = s; sh[1] = q; }
    }
    __syncthreads();
    float mu  = sh[0] * (1.f / D);
    float var = sh[1] * (1.f / D) - mu * mu;
    float rstd = rsqrtf(var + EPS);

    float4 g = ((const float4*)gamma)[t];
    float4 bb = ((const float4*)beta)[t];
    float4 o4;
    o4.x = (v.x - mu) * rstd * g.x + bb.x;
    o4.y = (v.y - mu) * rstd * g.y + bb.y;
    o4.z = (v.z - mu) * rstd * g.z + bb.z;
    o4.w = (v.w - mu) * rstd * g.w + bb.w;
    ((float4*)(out + (size_t)row * D))[t] = o4;
}

// ============================================================================
// launcher
// ============================================================================
#define ATTN_SMEM ((128 * 64 + 64 * KST + 64 * 64 + 128 * 64) * 4)

extern "C" void kernel_launch(void* const* d_in, const int* in_sizes, int n_in,
                              void* d_out, int out_size)
{
    const float* x     = (const float*)d_in[0];
    const float* Wq    = (const float*)d_in[1];
    const float* Wk    = (const float*)d_in[2];
    const float* Wv    = (const float*)d_in[3];
    const float* Wo    = (const float*)d_in[4];
    const float* bo    = (const float*)d_in[5];
    const float* gamma = (const float*)d_in[6];
    const float* beta  = (const float*)d_in[7];
    float* out = (float*)d_out;

    cudaFuncSetAttribute(attn_kernel,
                         cudaFuncAttributeMaxDynamicSharedMemorySize, ATTN_SMEM);

    qkv_kernel<<<dim3(M / 128, H, 3), 256>>>(x, Wq, Wk, Wv);
    attn_kernel<<<dim3(S / 128, B * H), 256, ATTN_SMEM>>>();
    proj_kernel<<<dim3(M / 128, D / 64), 256>>>(x, Wo, bo);
    ln_kernel<<<M, 256>>>(gamma, beta, out);
}

// round 3
// speedup vs baseline: 4.6036x; 4.6036x over previous
#include <cuda_runtime.h>
#include <math.h>
#include <stdint.h>

#define B 4
#define S 2048
#define D 1024
#define H 16
#define DH 64
#define M (B * S)          // 8192
#define EPS 1e-5f

// ---------------- scratch (no allocations allowed) ----------------
__device__ float g_q[(size_t)B * H * S * DH];     // [B,H,S,DH]
__device__ float g_k[(size_t)B * H * S * DH];
__device__ float g_v[(size_t)B * H * S * DH];
__device__ float g_ctx[(size_t)B * S * D];        // concat heads [B,S,D]
__device__ float g_tmp[(size_t)B * S * D];        // proj + residual, pre-LN

// ---------------- tf32 helpers ----------------
__device__ __forceinline__ uint32_t f2tf(float f) {
    uint32_t u;
    asm("cvt.rna.tf32.f32 %0, %1;" : "=r"(u) : "f"(f));
    return u;
}

// D = A(16x8,row) * B(8x8,col) + D, tf32 in, f32 accum
__device__ __forceinline__ void mma8(float4& c, const uint32_t a[4],
                                     uint32_t b0, uint32_t b1) {
    asm volatile(
        "mma.sync.aligned.m16n8k8.row.col.f32.tf32.tf32.f32 "
        "{%0,%1,%2,%3}, {%4,%5,%6,%7}, {%8,%9}, {%0,%1,%2,%3};"
        : "+f"(c.x), "+f"(c.y), "+f"(c.z), "+f"(c.w)
        : "r"(a[0]), "r"(a[1]), "r"(a[2]), "r"(a[3]), "r"(b0), "r"(b1));
}

// ============================================================================
// Kernel 1: QKV projection (TF32 MMA). grid (M/128, H, 3), block 256.
// C tile 128x64, warp grid 4x2 (warp tile 32x32), K-tile 32.
// ============================================================================
#define XS 36   // A-tile stride  (g multiplies stride -> stride%32==4)
#define WS 72   // B-tile stride  (tq multiplies stride -> stride%32==8)

__global__ __launch_bounds__(256) void qkv_tc(
    const float* __restrict__ x,
    const float* __restrict__ Wq,
    const float* __restrict__ Wk,
    const float* __restrict__ Wv)
{
    __shared__ __align__(16) uint32_t Xs[128 * XS];
    __shared__ __align__(16) uint32_t Ws[32 * WS];

    const int m0 = blockIdx.x * 128;
    const int h  = blockIdx.y;
    const float* W = (blockIdx.z == 0 ? Wq : (blockIdx.z == 1 ? Wk : Wv))
                     + (size_t)h * D * DH;
    float* outp = (blockIdx.z == 0 ? g_q : (blockIdx.z == 1 ? g_k : g_v));

    const int tid = threadIdx.x;
    const int w = tid >> 5, lane = tid & 31;
    const int g = lane >> 2, tq = lane & 3;
    const int wm = w >> 1, wn = w & 1;

    float4 acc[2][4];
    #pragma unroll
    for (int i = 0; i < 2; i++)
        #pragma unroll
        for (int j = 0; j < 4; j++) acc[i][j] = make_float4(0.f, 0.f, 0.f, 0.f);

    for (int k0 = 0; k0 < D; k0 += 32) {
        #pragma unroll
        for (int i = 0; i < 4; i++) {                 // X tile 128x32
            int idx = tid + 256 * i;                  // float4 idx 0..1023
            int r = idx >> 3, c = (idx & 7) * 4;
            float4 v = *(const float4*)&x[(size_t)(m0 + r) * D + k0 + c];
            *(uint4*)&Xs[r * XS + c] =
                make_uint4(f2tf(v.x), f2tf(v.y), f2tf(v.z), f2tf(v.w));
        }
        #pragma unroll
        for (int i = 0; i < 2; i++) {                 // W tile 32x64
            int idx = tid + 256 * i;                  // 0..511
            int r = idx >> 4, c = (idx & 15) * 4;
            float4 v = *(const float4*)&W[(size_t)(k0 + r) * DH + c];
            *(uint4*)&Ws[r * WS + c] =
                make_uint4(f2tf(v.x), f2tf(v.y), f2tf(v.z), f2tf(v.w));
        }
        __syncthreads();
        #pragma unroll
        for (int ks = 0; ks < 4; ks++) {
            const int k = ks * 8;
            uint32_t a[2][4];
            #pragma unroll
            for (int mt = 0; mt < 2; mt++) {
                int rm = wm * 32 + mt * 16;
                a[mt][0] = Xs[(rm + g) * XS + k + tq];
                a[mt][1] = Xs[(rm + g + 8) * XS + k + tq];
                a[mt][2] = Xs[(rm + g) * XS + k + tq + 4];
                a[mt][3] = Xs[(rm + g + 8) * XS + k + tq + 4];
            }
            #pragma unroll
            for (int nt = 0; nt < 4; nt++) {
                int nb = wn * 32 + nt * 8;
                uint32_t b0 = Ws[(k + tq) * WS + nb + g];
                uint32_t b1 = Ws[(k + tq + 4) * WS + nb + g];
                mma8(acc[0][nt], a[0], b0, b1);
                mma8(acc[1][nt], a[1], b0, b1);
            }
        }
        __syncthreads();
    }
    const int bb = m0 >> 11;                          // whole tile in one batch
    #pragma unroll
    for (int mt = 0; mt < 2; mt++) {
        int m = m0 + wm * 32 + mt * 16 + g;
        int s = m & (S - 1);
        size_t base0 = (((size_t)bb * H + h) * S + s) * DH;
        size_t base1 = (((size_t)bb * H + h) * S + s + 8) * DH;
        #pragma unroll
        for (int nt = 0; nt < 4; nt++) {
            int col = wn * 32 + nt * 8 + 2 * tq;
            *(float2*)&outp[base0 + col] = make_float2(acc[mt][nt].x, acc[mt][nt].y);
            *(float2*)&outp[base1 + col] = make_float2(acc[mt][nt].z, acc[mt][nt].w);
        }
    }
}

// ============================================================================
// Kernel 2: flash attention (TF32 MMA). grid (S/128, B*H), block 256.
// Q tile 128x64 (warp owns 16 rows), 64-key tiles, softmax in 4-lane groups,
// P staged through per-warp-private SMEM (tf32) for the PV MMA.
// ============================================================================
#define QS 68   // Q stride  (g * stride)
#define KS 68   // K stride  (n=8nt+g * stride)
#define VS 72   // V stride  (tq * stride)
#define PS 68   // P stride  (g * stride)
#define ATTN_SMEM ((128 * QS + 64 * KS + 64 * VS + 128 * PS) * 4)

__global__ __launch_bounds__(256, 2) void attn_tc()
{
    extern __shared__ __align__(16) uint32_t sm[];
    uint32_t* Qs = sm;                     // [128][QS]
    uint32_t* Ks = Qs + 128 * QS;          // [64][KS]
    uint32_t* Vs = Ks + 64 * KS;           // [64][VS]
    uint32_t* Ps = Vs + 64 * VS;           // [128][PS]

    const int bh = blockIdx.y;
    const int q0 = blockIdx.x * 128;
    const float* Qg = g_q + (size_t)bh * S * DH;
    const float* Kg = g_k + (size_t)bh * S * DH;
    const float* Vg = g_v + (size_t)bh * S * DH;

    const int tid = threadIdx.x;
    const int w = tid >> 5, lane = tid & 31;
    const int g = lane >> 2, tq = lane & 3;
    const int wq = w * 16;                 // warp's row band in the 128-tile

    // load Q (scaled by 1/sqrt(DH)=0.125, tf32)
    #pragma unroll
    for (int i = 0; i < 8; i++) {
        int idx = tid + 256 * i;           // float4 idx 0..2047
        int r = idx >> 4, c = (idx & 15) * 4;
        float4 v = *(const float4*)&Qg[(size_t)(q0 + r) * DH + c];
        *(uint4*)&Qs[r * QS + c] = make_uint4(
            f2tf(v.x * 0.125f), f2tf(v.y * 0.125f),
            f2tf(v.z * 0.125f), f2tf(v.w * 0.125f));
    }

    float m_run[2] = { -1e30f, -1e30f };
    float l_run[2] = { 0.f, 0.f };
    float4 oacc[8];
    #pragma unroll
    for (int i = 0; i < 8; i++) oacc[i] = make_float4(0.f, 0.f, 0.f, 0.f);

    for (int kt = 0; kt < S; kt += 64) {
        __syncthreads();                   // previous PV done before overwrite
        #pragma unroll
        for (int i = 0; i < 4; i++) {      // K tile 64x64
            int idx = tid + 256 * i;
            int r = idx >> 4, c = (idx & 15) * 4;
            float4 v = *(const float4*)&Kg[(size_t)(kt + r) * DH + c];
            *(uint4*)&Ks[r * KS + c] =
                make_uint4(f2tf(v.x), f2tf(v.y), f2tf(v.z), f2tf(v.w));
        }
        #pragma unroll
        for (int i = 0; i < 4; i++) {      // V tile 64x64
            int idx = tid + 256 * i;
            int r = idx >> 4, c = (idx & 15) * 4;
            float4 v = *(const float4*)&Vg[(size_t)(kt + r) * DH + c];
            *(uint4*)&Vs[r * VS + c] =
                make_uint4(f2tf(v.x), f2tf(v.y), f2tf(v.z), f2tf(v.w));
        }
        __syncthreads();

        // ---- scores S = Q @ K^T  (per warp: 16 x 64) ----
        float4 sacc[8];
        #pragma unroll
        for (int i = 0; i < 8; i++) sacc[i] = make_float4(0.f, 0.f, 0.f, 0.f);

        #pragma unroll
        for (int ks = 0; ks < 8; ks++) {
            const int k = ks * 8;
            uint32_t a[4];
            a[0] = Qs[(wq + g) * QS + k + tq];
            a[1] = Qs[(wq + g + 8) * QS + k + tq];
            a[2] = Qs[(wq + g) * QS + k + tq + 4];
            a[3] = Qs[(wq + g + 8) * QS + k + tq + 4];
            #pragma unroll
            for (int nt = 0; nt < 8; nt++) {
                uint32_t b0 = Ks[(nt * 8 + g) * KS + k + tq];
                uint32_t b1 = Ks[(nt * 8 + g) * KS + k + tq + 4];
                mma8(sacc[nt], a, b0, b1);
            }
        }

        // ---- online softmax (rows wq+g and wq+g+8) ----
        float tm0 = -1e30f, tm1 = -1e30f;
        #pragma unroll
        for (int nt = 0; nt < 8; nt++) {
            tm0 = fmaxf(tm0, fmaxf(sacc[nt].x, sacc[nt].y));
            tm1 = fmaxf(tm1, fmaxf(sacc[nt].z, sacc[nt].w));
        }
        tm0 = fmaxf(tm0, __shfl_xor_sync(0xffffffffu, tm0, 1));
        tm0 = fmaxf(tm0, __shfl_xor_sync(0xffffffffu, tm0, 2));
        tm1 = fmaxf(tm1, __shfl_xor_sync(0xffffffffu, tm1, 1));
        tm1 = fmaxf(tm1, __shfl_xor_sync(0xffffffffu, tm1, 2));

        float mn0 = fmaxf(m_run[0], tm0);
        float mn1 = fmaxf(m_run[1], tm1);
        float al0 = __expf(m_run[0] - mn0);
        float al1 = __expf(m_run[1] - mn1);
        m_run[0] = mn0; m_run[1] = mn1;

        float rs0 = 0.f, rs1 = 0.f;
        #pragma unroll
        for (int nt = 0; nt < 8; nt++) {
            float p0 = __expf(sacc[nt].x - mn0);
            float p1 = __expf(sacc[nt].y - mn0);
            float p2 = __expf(sacc[nt].z - mn1);
            float p3 = __expf(sacc[nt].w - mn1);
            rs0 += p0 + p1; rs1 += p2 + p3;
            int col = nt * 8 + 2 * tq;
            *(uint2*)&Ps[(wq + g) * PS + col]     = make_uint2(f2tf(p0), f2tf(p1));
            *(uint2*)&Ps[(wq + g + 8) * PS + col] = make_uint2(f2tf(p2), f2tf(p3));
        }
        rs0 += __shfl_xor_sync(0xffffffffu, rs0, 1);
        rs0 += __shfl_xor_sync(0xffffffffu, rs0, 2);
        rs1 += __shfl_xor_sync(0xffffffffu, rs1, 1);
        rs1 += __shfl_xor_sync(0xffffffffu, rs1, 2);
        l_run[0] = l_run[0] * al0 + rs0;
        l_run[1] = l_run[1] * al1 + rs1;
        #pragma unroll
        for (int nt = 0; nt < 8; nt++) {
            oacc[nt].x *= al0; oacc[nt].y *= al0;
            oacc[nt].z *= al1; oacc[nt].w *= al1;
        }
        __syncwarp();                       // P visible within warp

        // ---- PV: oacc += P @ V ----
        #pragma unroll
        for (int ks = 0; ks < 8; ks++) {
            const int k = ks * 8;
            uint32_t a[4];
            a[0] = Ps[(wq + g) * PS + k + tq];
            a[1] = Ps[(wq + g + 8) * PS + k + tq];
            a[2] = Ps[(wq + g) * PS + k + tq + 4];
            a[3] = Ps[(wq + g + 8) * PS + k + tq + 4];
            #pragma unroll
            for (int nt = 0; nt < 8; nt++) {
                uint32_t b0 = Vs[(k + tq) * VS + nt * 8 + g];
                uint32_t b1 = Vs[(k + tq + 4) * VS + nt * 8 + g];
                mma8(oacc[nt], a, b0, b1);
            }
        }
    }

    // ---- epilogue: normalize, write concat layout [B,S,D] ----
    const int bb = bh >> 4, h = bh & 15;
    const float inv0 = 1.f / l_run[0];
    const float inv1 = 1.f / l_run[1];
    const int r0 = q0 + wq + g;
    size_t base0 = ((size_t)bb * S + r0) * D + h * DH;
    size_t base1 = ((size_t)bb * S + r0 + 8) * D + h * DH;
    #pragma unroll
    for (int nt = 0; nt < 8; nt++) {
        int col = nt * 8 + 2 * tq;
        *(float2*)&g_ctx[base0 + col] = make_float2(oacc[nt].x * inv0, oacc[nt].y * inv0);
        *(float2*)&g_ctx[base1 + col] = make_float2(oacc[nt].z * inv1, oacc[nt].w * inv1);
    }
}

// ============================================================================
// Kernel 3: output projection + bias + residual (TF32 MMA).
// grid (M/128, D/64), block 256.  g_tmp = g_ctx @ Wo + bo + x
// ============================================================================
__global__ __launch_bounds__(256) void proj_tc(
    const float* __restrict__ x,
    const float* __restrict__ Wo,
    const float* __restrict__ bo)
{
    __shared__ __align__(16) uint32_t Xs[128 * XS];
    __shared__ __align__(16) uint32_t Ws[32 * WS];

    const int m0 = blockIdx.x * 128;
    const int n0 = blockIdx.y * 64;

    const int tid = threadIdx.x;
    const int w = tid >> 5, lane = tid & 31;
    const int g = lane >> 2, tq = lane & 3;
    const int wm = w >> 1, wn = w & 1;

    float4 acc[2][4];
    #pragma unroll
    for (int i = 0; i < 2; i++)
        #pragma unroll
        for (int j = 0; j < 4; j++) acc[i][j] = make_float4(0.f, 0.f, 0.f, 0.f);

    for (int k0 = 0; k0 < D; k0 += 32) {
        #pragma unroll
        for (int i = 0; i < 4; i++) {
            int idx = tid + 256 * i;
            int r = idx >> 3, c = (idx & 7) * 4;
            float4 v = *(const float4*)&g_ctx[(size_t)(m0 + r) * D + k0 + c];
            *(uint4*)&Xs[r * XS + c] =
                make_uint4(f2tf(v.x), f2tf(v.y), f2tf(v.z), f2tf(v.w));
        }
        #pragma unroll
        for (int i = 0; i < 2; i++) {
            int idx = tid + 256 * i;
            int r = idx >> 4, c = (idx & 15) * 4;
            float4 v = *(const float4*)&Wo[(size_t)(k0 + r) * D + n0 + c];
            *(uint4*)&Ws[r * WS + c] =
                make_uint4(f2tf(v.x), f2tf(v.y), f2tf(v.z), f2tf(v.w));
        }
        __syncthreads();
        #pragma unroll
        for (int ks = 0; ks < 4; ks++) {
            const int k = ks * 8;
            uint32_t a[2][4];
            #pragma unroll
            for (int mt = 0; mt < 2; mt++) {
                int rm = wm * 32 + mt * 16;
                a[mt][0] = Xs[(rm + g) * XS + k + tq];
                a[mt][1] = Xs[(rm + g + 8) * XS + k + tq];
                a[mt][2] = Xs[(rm + g) * XS + k + tq + 4];
                a[mt][3] = Xs[(rm + g + 8) * XS + k + tq + 4];
            }
            #pragma unroll
            for (int nt = 0; nt < 4; nt++) {
                int nb = wn * 32 + nt * 8;
                uint32_t b0 = Ws[(k + tq) * WS + nb + g];
                uint32_t b1 = Ws[(k + tq + 4) * WS + nb + g];
                mma8(acc[0][nt], a[0], b0, b1);
                mma8(acc[1][nt], a[1], b0, b1);
            }
        }
        __syncthreads();
    }
    #pragma unroll
    for (int mt = 0; mt < 2; mt++) {
        int m = m0 + wm * 32 + mt * 16 + g;
        #pragma unroll
        for (int nt = 0; nt < 4; nt++) {
            int col = n0 + wn * 32 + nt * 8 + 2 * tq;
            float2 b2 = *(const float2*)&bo[col];
            float2 x0 = *(const float2*)&x[(size_t)m * D + col];
            float2 x1 = *(const float2*)&x[(size_t)(m + 8) * D + col];
            *(float2*)&g_tmp[(size_t)m * D + col] =
                make_float2(acc[mt][nt].x + b2.x + x0.x, acc[mt][nt].y + b2.y + x0.y);
            *(float2*)&g_tmp[(size_t)(m + 8) * D + col] =
                make_float2(acc[mt][nt].z + b2.x + x1.x, acc[mt][nt].w + b2.y + x1.y);
        }
    }
}

// ============================================================================
// Kernel 4: LayerNorm per row.  grid M, block 256 (4 floats / thread).
// ============================================================================
__global__ __launch_bounds__(256) void ln_kernel(
    const float* __restrict__ gamma,
    const float* __restrict__ beta,
    float* __restrict__ out)
{
    const int row = blockIdx.x;
    const int t = threadIdx.x;
    const float4* src = (const float4*)(g_tmp + (size_t)row * D);
    float4 v = src[t];

    float s = v.x + v.y + v.z + v.w;
    float q = v.x * v.x + v.y * v.y + v.z * v.z + v.w * v.w;
    #pragma unroll
    for (int o = 16; o > 0; o >>= 1) {
        s += __shfl_xor_sync(0xffffffffu, s, o);
        q += __shfl_xor_sync(0xffffffffu, q, o);
    }
    __shared__ float sh[16];
    int w = t >> 5, lane = t & 31;
    if (lane == 0) { sh[w] = s; sh[8 + w] = q; }
    __syncthreads();
    if (t < 32) {
        s = (lane < 8) ? sh[lane] : 0.f;
        q = (lane < 8) ? sh[8 + lane] : 0.f;
        #pragma unroll
        for (int o = 4; o > 0; o >>= 1) {
            s += __shfl_xor_sync(0xffffffffu, s, o);
            q += __shfl_xor_sync(0xffffffffu, q, o);
        }
        if (lane == 0) { sh[0] = s; sh[1] = q; }
    }
    __syncthreads();
    float mu  = sh[0] * (1.f / D);
    float var = sh[1] * (1.f / D) - mu * mu;
    float rstd = rsqrtf(var + EPS);

    float4 g = ((const float4*)gamma)[t];
    float4 bb = ((const float4*)beta)[t];
    float4 o4;
    o4.x = (v.x - mu) * rstd * g.x + bb.x;
    o4.y = (v.y - mu) * rstd * g.y + bb.y;
    o4.z = (v.z - mu) * rstd * g.z + bb.z;
    o4.w = (v.w - mu) * rstd * g.w + bb.w;
    ((float4*)(out + (size_t)row * D))[t] = o4;
}

// ============================================================================
// launcher
// ============================================================================
extern "C" void kernel_launch(void* const* d_in, const int* in_sizes, int n_in,
                              void* d_out, int out_size)
{
    const float* x     = (const float*)d_in[0];
    const float* Wq    = (const float*)d_in[1];
    const float* Wk    = (const float*)d_in[2];
    const float* Wv    = (const float*)d_in[3];
    const float* Wo    = (const float*)d_in[4];
    const float* bo    = (const float*)d_in[5];
    const float* gamma = (const float*)d_in[6];
    const float* beta  = (const float*)d_in[7];
    float* out = (float*)d_out;

    cudaFuncSetAttribute(attn_tc,
                         cudaFuncAttributeMaxDynamicSharedMemorySize, ATTN_SMEM);

    qkv_tc<<<dim3(M / 128, H, 3), 256>>>(x, Wq, Wk, Wv);
    attn_tc<<<dim3(S / 128, B * H), 256, ATTN_SMEM>>>();
    proj_tc<<<dim3(M / 128, D / 64), 256>>>(x, Wo, bo);
    ln_kernel<<<M, 256>>>(gamma, beta, out);
}

// round 6
// speedup vs baseline: 7.7901x; 1.6922x over previous
#include <cuda_runtime.h>
#include <math.h>
#include <stdint.h>

#define B 4
#define S 2048
#define D 1024
#define H 16
#define DH 64
#define M (B * S)          // 8192
#define EPS 1e-5f

// ---------------- scratch (no allocations allowed) ----------------
__device__ uint32_t g_qh[(size_t)B * H * S * 32];   // Q bf16x2 pairs [bh][s][dhp], pre-scaled by 0.125
__device__ uint32_t g_kt[(size_t)B * H * 32 * S];   // K bf16x2 pairs TRANSPOSED [bh][dhp][s]
__device__ uint32_t g_vh[(size_t)B * H * S * 32];   // V bf16x2 pairs [bh][s][dhp]
__device__ float    g_ctx[(size_t)B * S * D];       // concat heads [B,S,D]
__device__ float    g_tmp[(size_t)B * S * D];       // proj + residual, pre-LN

// ---------------- helpers ----------------
__device__ __forceinline__ uint32_t f2bf2(float lo, float hi) {
    uint32_t d;
    asm("cvt.rn.bf16x2.f32 %0, %1, %2;" : "=r"(d) : "f"(hi), "f"(lo));
    return d;
}
__device__ __forceinline__ uint32_t prmt(uint32_t a, uint32_t b, uint32_t s) {
    uint32_t d;
    asm("prmt.b32 %0, %1, %2, %3;" : "=r"(d) : "r"(a), "r"(b), "r"(s));
    return d;
}
// D = A(16x16,row) * B(16x8,col) + D, bf16 in, f32 accum
__device__ __forceinline__ void mma16(float4& c, const uint32_t a[4],
                                      uint32_t b0, uint32_t b1) {
    asm volatile(
        "mma.sync.aligned.m16n8k16.row.col.f32.bf16.bf16.f32 "
        "{%0,%1,%2,%3}, {%4,%5,%6,%7}, {%8,%9}, {%0,%1,%2,%3};"
        : "+f"(c.x), "+f"(c.y), "+f"(c.z), "+f"(c.w)
        : "r"(a[0]), "r"(a[1]), "r"(a[2]), "r"(a[3]), "r"(b0), "r"(b1));
}

// ============================================================================
// Kernel 1: QKV projection (bf16 MMA). grid (M/128, H, 3), block 256.
// C tile 128x64, warp grid 4x2 (warp tile 32x32), K-tile 32 (2 MMA k-steps).
// A: Xs[row][kp] stride 20 (=4 mod 32). B: Wp[kp][n] stride 72 (=8 mod 32).
// ============================================================================
#define XSB 20
#define WSB 72

__global__ __launch_bounds__(256) void qkv_tc(
    const float* __restrict__ x,
    const float* __restrict__ Wq,
    const float* __restrict__ Wk,
    const float* __restrict__ Wv)
{
    __shared__ __align__(16) uint32_t Xs[128 * XSB];
    __shared__ __align__(16) uint32_t Wp[16 * WSB];

    const int m0 = blockIdx.x * 128;
    const int h  = blockIdx.y;
    const int z  = blockIdx.z;
    const float* W = (z == 0 ? Wq : (z == 1 ? Wk : Wv)) + (size_t)h * D * DH;

    const int tid = threadIdx.x;
    const int w = tid >> 5, lane = tid & 31;
    const int g = lane >> 2, tq = lane & 3;
    const int wm = w >> 1, wn = w & 1;

    const int xr_r = tid >> 3, xr_c = (tid & 7) * 4;  // X staging coords
    const int wk_p = tid >> 4, wk_c = (tid & 15) * 4; // W staging coords

    float4 xr[4], wr0, wr1;

    auto ldX = [&](int k0) {
        #pragma unroll
        for (int i = 0; i < 4; i++)
            xr[i] = *(const float4*)&x[(size_t)(m0 + xr_r + 32 * i) * D + k0 + xr_c];
    };
    auto ldW = [&](int k0) {
        wr0 = *(const float4*)&W[(size_t)(k0 + 2 * wk_p) * DH + wk_c];
        wr1 = *(const float4*)&W[(size_t)(k0 + 2 * wk_p + 1) * DH + wk_c];
    };
    auto stXW = [&]() {
        #pragma unroll
        for (int i = 0; i < 4; i++)
            *(uint2*)&Xs[(xr_r + 32 * i) * XSB + (xr_c >> 1)] =
                make_uint2(f2bf2(xr[i].x, xr[i].y), f2bf2(xr[i].z, xr[i].w));
        *(uint4*)&Wp[wk_p * WSB + wk_c] =
            make_uint4(f2bf2(wr0.x, wr1.x), f2bf2(wr0.y, wr1.y),
                       f2bf2(wr0.z, wr1.z), f2bf2(wr0.w, wr1.w));
    };

    float4 acc[2][4];
    #pragma unroll
    for (int i = 0; i < 2; i++)
        #pragma unroll
        for (int j = 0; j < 4; j++) acc[i][j] = make_float4(0.f, 0.f, 0.f, 0.f);

    ldX(0); ldW(0);
    stXW();
    __syncthreads();

    for (int k0 = 0; k0 < D; k0 += 32) {
        const bool nxt = (k0 + 32 < D);
        if (nxt) { ldX(k0 + 32); ldW(k0 + 32); }
        #pragma unroll
        for (int ks = 0; ks < 2; ks++) {
            const int kp0 = ks * 8;
            uint32_t a[2][4];
            #pragma unroll
            for (int mt = 0; mt < 2; mt++) {
                int rm = wm * 32 + mt * 16;
                a[mt][0] = Xs[(rm + g) * XSB + kp0 + tq];
                a[mt][1] = Xs[(rm + g + 8) * XSB + kp0 + tq];
                a[mt][2] = Xs[(rm + g) * XSB + kp0 + 4 + tq];
                a[mt][3] = Xs[(rm + g + 8) * XSB + kp0 + 4 + tq];
            }
            #pragma unroll
            for (int nt = 0; nt < 4; nt++) {
                int nb = wn * 32 + nt * 8;
                uint32_t b0 = Wp[(kp0 + tq) * WSB + nb + g];
                uint32_t b1 = Wp[(kp0 + 4 + tq) * WSB + nb + g];
                mma16(acc[0][nt], a[0], b0, b1);
                mma16(acc[1][nt], a[1], b0, b1);
            }
        }
        __syncthreads();
        if (nxt) { stXW(); __syncthreads(); }
    }

    // epilogue: pack to bf16x2 and store
    const int bb = m0 >> 11;
    const float qs = (z == 0) ? 0.125f : 1.0f;
    #pragma unroll
    for (int mt = 0; mt < 2; mt++) {
        int m = m0 + wm * 32 + mt * 16 + g;
        int s = m & (S - 1);
        #pragma unroll
        for (int nt = 0; nt < 4; nt++) {
            int dhp = wn * 16 + nt * 4 + tq;
            uint32_t u0 = f2bf2(acc[mt][nt].x * qs, acc[mt][nt].y * qs);
            uint32_t u1 = f2bf2(acc[mt][nt].z * qs, acc[mt][nt].w * qs);
            if (z == 1) {   // K transposed [bh][dhp][s]
                size_t base = ((size_t)(bb * H + h) * 32 + dhp) * S;
                g_kt[base + s]     = u0;
                g_kt[base + s + 8] = u1;
            } else {
                uint32_t* outp = (z == 0) ? g_qh : g_vh;
                size_t base = ((size_t)(bb * H + h) * S + s) * 32;
                outp[base + dhp]          = u0;
                outp[base + 8 * 32 + dhp] = u1;
            }
        }
    }
}

// ============================================================================
// Kernel 2: flash attention (bf16 MMA). grid (S/128, B*H), block 256.
// Warp owns 16 q-rows. 64-key tiles. A: Qs/Ps stride 36; B: Kp/Vp stride 72.
// ============================================================================
#define QSB 36
#define KPB 72
#define VPB 72
#define PSB 36
#define ATTN_SMEM ((128 * QSB + 32 * KPB + 32 * VPB + 128 * PSB) * 4)

__global__ __launch_bounds__(256, 2) void attn_tc()
{
    extern __shared__ __align__(16) uint32_t sm[];
    uint32_t* Qs = sm;                      // [128][QSB]
    uint32_t* Kp = Qs + 128 * QSB;          // [32][KPB]   (dh-pair rows, s cols)
    uint32_t* Vp = Kp + 32 * KPB;           // [32][VPB]   (s-pair rows, dh cols)
    uint32_t* Ps = Vp + 32 * VPB;           // [128][PSB]

    const int bh = blockIdx.y;
    const int q0 = blockIdx.x * 128;
    const uint32_t* Qg = g_qh + (size_t)bh * S * 32;
    const uint32_t* Kt = g_kt + (size_t)bh * 32 * S;
    const uint32_t* Vh = g_vh + (size_t)bh * S * 32;

    const int tid = threadIdx.x;
    const int w = tid >> 5, lane = tid & 31;
    const int g = lane >> 2, tq = lane & 3;
    const int wq = w * 16;

    // ---- stage Q (straight copy of bf16 pairs, already scaled) ----
    {
        const int r = tid >> 3, c = (tid & 7) * 4;
        #pragma unroll
        for (int i = 0; i < 4; i++) {
            uint4 v = *(const uint4*)&Qg[(size_t)(q0 + r + 32 * i) * 32 + c];
            *(uint4*)&Qs[(r + 32 * i) * QSB + c] = v;
        }
    }

    // K/V prefetch registers
    uint4 kr[2];
    uint32_t va[4], vb[4];
    const int k_dhp = tid >> 4, k_c = (tid & 15) * 4;   // K staging coords
    const int v_dhp = tid & 31;                          // V staging coords

    auto ldKV = [&](int kt) {
        #pragma unroll
        for (int i = 0; i < 2; i++)
            kr[i] = *(const uint4*)&Kt[(size_t)(k_dhp + 16 * i) * S + kt + k_c];
        #pragma unroll
        for (int i = 0; i < 4; i++) {
            int sp = (tid >> 5) + 8 * i;
            va[i] = Vh[(size_t)(kt + 2 * sp) * 32 + v_dhp];
            vb[i] = Vh[(size_t)(kt + 2 * sp + 1) * 32 + v_dhp];
        }
    };
    auto stKV = [&]() {
        #pragma unroll
        for (int i = 0; i < 2; i++)
            *(uint4*)&Kp[(k_dhp + 16 * i) * KPB + k_c] = kr[i];
        #pragma unroll
        for (int i = 0; i < 4; i++) {
            int sp = (tid >> 5) + 8 * i;
            *(uint2*)&Vp[sp * VPB + 2 * v_dhp] =
                make_uint2(prmt(va[i], vb[i], 0x5410), prmt(va[i], vb[i], 0x7632));
        }
    };

    float m_run[2] = { -1e30f, -1e30f };
    float l_run[2] = { 0.f, 0.f };
    float4 oacc[8];
    #pragma unroll
    for (int i = 0; i < 8; i++) oacc[i] = make_float4(0.f, 0.f, 0.f, 0.f);

    ldKV(0);
    stKV();
    __syncthreads();

    for (int kt = 0; kt < S; kt += 64) {
        const bool nxt = (kt + 64 < S);
        if (nxt) ldKV(kt + 64);

        // ---- scores S = Q @ K^T  (16 x 64 per warp) ----
        float4 sacc[8];
        #pragma unroll
        for (int i = 0; i < 8; i++) sacc[i] = make_float4(0.f, 0.f, 0.f, 0.f);

        #pragma unroll
        for (int ks = 0; ks < 4; ks++) {
            const int kp0 = ks * 8;
            uint32_t a[4];
            a[0] = Qs[(wq + g) * QSB + kp0 + tq];
            a[1] = Qs[(wq + g + 8) * QSB + kp0 + tq];
            a[2] = Qs[(wq + g) * QSB + kp0 + 4 + tq];
            a[3] = Qs[(wq + g + 8) * QSB + kp0 + 4 + tq];
            #pragma unroll
            for (int nt = 0; nt < 8; nt++) {
                uint32_t b0 = Kp[(kp0 + tq) * KPB + nt * 8 + g];
                uint32_t b1 = Kp[(kp0 + 4 + tq) * KPB + nt * 8 + g];
                mma16(sacc[nt], a, b0, b1);
            }
        }

        // ---- online softmax (rows wq+g, wq+g+8) ----
        float tm0 = -1e30f, tm1 = -1e30f;
        #pragma unroll
        for (int nt = 0; nt < 8; nt++) {
            tm0 = fmaxf(tm0, fmaxf(sacc[nt].x, sacc[nt].y));
            tm1 = fmaxf(tm1, fmaxf(sacc[nt].z, sacc[nt].w));
        }
        tm0 = fmaxf(tm0, __shfl_xor_sync(0xffffffffu, tm0, 1));
        tm0 = fmaxf(tm0, __shfl_xor_sync(0xffffffffu, tm0, 2));
        tm1 = fmaxf(tm1, __shfl_xor_sync(0xffffffffu, tm1, 1));
        tm1 = fmaxf(tm1, __shfl_xor_sync(0xffffffffu, tm1, 2));

        float mn0 = fmaxf(m_run[0], tm0);
        float mn1 = fmaxf(m_run[1], tm1);
        float al0 = __expf(m_run[0] - mn0);
        float al1 = __expf(m_run[1] - mn1);
        m_run[0] = mn0; m_run[1] = mn1;

        float rs0 = 0.f, rs1 = 0.f;
        #pragma unroll
        for (int nt = 0; nt < 8; nt++) {
            float p0 = __expf(sacc[nt].x - mn0);
            float p1 = __expf(sacc[nt].y - mn0);
            float p2 = __expf(sacc[nt].z - mn1);
            float p3 = __expf(sacc[nt].w - mn1);
            rs0 += p0 + p1; rs1 += p2 + p3;
            Ps[(wq + g) * PSB + nt * 4 + tq]     = f2bf2(p0, p1);
            Ps[(wq + g + 8) * PSB + nt * 4 + tq] = f2bf2(p2, p3);
        }
        rs0 += __shfl_xor_sync(0xffffffffu, rs0, 1);
        rs0 += __shfl_xor_sync(0xffffffffu, rs0, 2);
        rs1 += __shfl_xor_sync(0xffffffffu, rs1, 1);
        rs1 += __shfl_xor_sync(0xffffffffu, rs1, 2);
        l_run[0] = l_run[0] * al0 + rs0;
        l_run[1] = l_run[1] * al1 + rs1;
        #pragma unroll
        for (int nt = 0; nt < 8; nt++) {
            oacc[nt].x *= al0; oacc[nt].y *= al0;
            oacc[nt].z *= al1; oacc[nt].w *= al1;
        }
        __syncwarp();

        // ---- PV: oacc += P @ V ----
        #pragma unroll
        for (int ks = 0; ks < 4; ks++) {
            const int kp0 = ks * 8;
            uint32_t a[4];
            a[0] = Ps[(wq + g) * PSB + kp0 + tq];
            a[1] = Ps[(wq + g + 8) * PSB + kp0 + tq];
            a[2] = Ps[(wq + g) * PSB + kp0 + 4 + tq];
            a[3] = Ps[(wq + g + 8) * PSB + kp0 + 4 + tq];
            #pragma unroll
            for (int nt = 0; nt < 8; nt++) {
                uint32_t b0 = Vp[(kp0 + tq) * VPB + nt * 8 + g];
                uint32_t b1 = Vp[(kp0 + 4 + tq) * VPB + nt * 8 + g];
                mma16(oacc[nt], a, b0, b1);
            }
        }
        __syncthreads();
        if (nxt) { stKV(); __syncthreads(); }
    }

    // ---- epilogue: normalize, write concat layout [B,S,D] (f32) ----
    const int bb = bh >> 4, h = bh & 15;
    const float inv0 = 1.f / l_run[0];
    const float inv1 = 1.f / l_run[1];
    const int r0 = q0 + wq + g;
    size_t base0 = ((size_t)bb * S + r0) * D + h * DH;
    size_t base1 = ((size_t)bb * S + r0 + 8) * D + h * DH;
    #pragma unroll
    for (int nt = 0; nt < 8; nt++) {
        int col = nt * 8 + 2 * tq;
        *(float2*)&g_ctx[base0 + col] = make_float2(oacc[nt].x * inv0, oacc[nt].y * inv0);
        *(float2*)&g_ctx[base1 + col] = make_float2(oacc[nt].z * inv1, oacc[nt].w * inv1);
    }
}

// ============================================================================
// Kernel 3: output projection + bias + residual (bf16 MMA).
// grid (M/128, D/64), block 256.  g_tmp = g_ctx @ Wo + bo + x
// ============================================================================
__global__ __launch_bounds__(256) void proj_tc(
    const float* __restrict__ x,
    const float* __restrict__ Wo,
    const float* __restrict__ bo)
{
    __shared__ __align__(16) uint32_t Xs[128 * XSB];
    __shared__ __align__(16) uint32_t Wp[16 * WSB];

    const int m0 = blockIdx.x * 128;
    const int n0 = blockIdx.y * 64;

    const int tid = threadIdx.x;
    const int w = tid >> 5, lane = tid & 31;
    const int g = lane >> 2, tq = lane & 3;
    const int wm = w >> 1, wn = w & 1;

    const int xr_r = tid >> 3, xr_c = (tid & 7) * 4;
    const int wk_p = tid >> 4, wk_c = (tid & 15) * 4;

    float4 xr[4], wr0, wr1;

    auto ldX = [&](int k0) {
        #pragma unroll
        for (int i = 0; i < 4; i++)
            xr[i] = *(const float4*)&g_ctx[(size_t)(m0 + xr_r + 32 * i) * D + k0 + xr_c];
    };
    auto ldW = [&](int k0) {
        wr0 = *(const float4*)&Wo[(size_t)(k0 + 2 * wk_p) * D + n0 + wk_c];
        wr1 = *(const float4*)&Wo[(size_t)(k0 + 2 * wk_p + 1) * D + n0 + wk_c];
    };
    auto stXW = [&]() {
        #pragma unroll
        for (int i = 0; i < 4; i++)
            *(uint2*)&Xs[(xr_r + 32 * i) * XSB + (xr_c >> 1)] =
                make_uint2(f2bf2(xr[i].x, xr[i].y), f2bf2(xr[i].z, xr[i].w));
        *(uint4*)&Wp[wk_p * WSB + wk_c] =
            make_uint4(f2bf2(wr0.x, wr1.x), f2bf2(wr0.y, wr1.y),
                       f2bf2(wr0.z, wr1.z), f2bf2(wr0.w, wr1.w));
    };

    float4 acc[2][4];
    #pragma unroll
    for (int i = 0; i < 2; i++)
        #pragma unroll
        for (int j = 0; j < 4; j++) acc[i][j] = make_float4(0.f, 0.f, 0.f, 0.f);

    ldX(0); ldW(0);
    stXW();
    __syncthreads();

    for (int k0 = 0; k0 < D; k0 += 32) {
        const bool nxt = (k0 + 32 < D);
        if (nxt) { ldX(k0 + 32); ldW(k0 + 32); }
        #pragma unroll
        for (int ks = 0; ks < 2; ks++) {
            const int kp0 = ks * 8;
            uint32_t a[2][4];
            #pragma unroll
            for (int mt = 0; mt < 2; mt++) {
                int rm = wm * 32 + mt * 16;
                a[mt][0] = Xs[(rm + g) * XSB + kp0 + tq];
                a[mt][1] = Xs[(rm + g + 8) * XSB + kp0 + tq];
                a[mt][2] = Xs[(rm + g) * XSB + kp0 + 4 + tq];
                a[mt][3] = Xs[(rm + g + 8) * XSB + kp0 + 4 + tq];
            }
            #pragma unroll
            for (int nt = 0; nt < 4; nt++) {
                int nb = wn * 32 + nt * 8;
                uint32_t b0 = Wp[(kp0 + tq) * WSB + nb + g];
                uint32_t b1 = Wp[(kp0 + 4 + tq) * WSB + nb + g];
                mma16(acc[0][nt], a[0], b0, b1);
                mma16(acc[1][nt], a[1], b0, b1);
            }
        }
        __syncthreads();
        if (nxt) { stXW(); __syncthreads(); }
    }

    #pragma unroll
    for (int mt = 0; mt < 2; mt++) {
        int m = m0 + wm * 32 + mt * 16 + g;
        #pragma unroll
        for (int nt = 0; nt < 4; nt++) {
            int col = n0 + wn * 32 + nt * 8 + 2 * tq;
            float2 b2 = *(const float2*)&bo[col];
            float2 x0 = *(const float2*)&x[(size_t)m * D + col];
            float2 x1 = *(const float2*)&x[(size_t)(m + 8) * D + col];
            *(float2*)&g_tmp[(size_t)m * D + col] =
                make_float2(acc[mt][nt].x + b2.x + x0.x, acc[mt][nt].y + b2.y + x0.y);
            *(float2*)&g_tmp[(size_t)(m + 8) * D + col] =
                make_float2(acc[mt][nt].z + b2.x + x1.x, acc[mt][nt].w + b2.y + x1.y);
        }
    }
}

// ============================================================================
// Kernel 4: LayerNorm per row.  grid M, block 256 (4 floats / thread).
// ============================================================================
__global__ __launch_bounds__(256) void ln_kernel(
    const float* __restrict__ gamma,
    const float* __restrict__ beta,
    float* __restrict__ out)
{
    const int row = blockIdx.x;
    const int t = threadIdx.x;
    const float4* src = (const float4*)(g_tmp + (size_t)row * D);
    float4 v = src[t];

    float s = v.x + v.y + v.z + v.w;
    float q = v.x * v.x + v.y * v.y + v.z * v.z + v.w * v.w;
    #pragma unroll
    for (int o = 16; o > 0; o >>= 1) {
        s += __shfl_xor_sync(0xffffffffu, s, o);
        q += __shfl_xor_sync(0xffffffffu, q, o);
    }
    __shared__ float sh[16];
    int w = t >> 5, lane = t & 31;
    if (lane == 0) { sh[w] = s; sh[8 + w] = q; }
    __syncthreads();
    if (t < 32) {
        s = (lane < 8) ? sh[lane] : 0.f;
        q = (lane < 8) ? sh[8 + lane] : 0.f;
        #pragma unroll
        for (int o = 4; o > 0; o >>= 1) {
            s += __shfl_xor_sync(0xffffffffu, s, o);
            q += __shfl_xor_sync(0xffffffffu, q, o);
        }
        if (lane == 0) { sh[0] = s; sh[1] = q; }
    }
    __syncthreads();
    float mu  = sh[0] * (1.f / D);
    float var = sh[1] * (1.f / D) - mu * mu;
    float rstd = rsqrtf(var + EPS);

    float4 g = ((const float4*)gamma)[t];
    float4 bb = ((const float4*)beta)[t];
    float4 o4;
    o4.x = (v.x - mu) * rstd * g.x + bb.x;
    o4.y = (v.y - mu) * rstd * g.y + bb.y;
    o4.z = (v.z - mu) * rstd * g.z + bb.z;
    o4.w = (v.w - mu) * rstd * g.w + bb.w;
    ((float4*)(out + (size_t)row * D))[t] = o4;
}

// ============================================================================
// launcher
// ============================================================================
extern "C" void kernel_launch(void* const* d_in, const int* in_sizes, int n_in,
                              void* d_out, int out_size)
{
    const float* x     = (const float*)d_in[0];
    const float* Wq    = (const float*)d_in[1];
    const float* Wk    = (const float*)d_in[2];
    const float* Wv    = (const float*)d_in[3];
    const float* Wo    = (const float*)d_in[4];
    const float* bo    = (const float*)d_in[5];
    const float* gamma = (const float*)d_in[6];
    const float* beta  = (const float*)d_in[7];
    float* out = (float*)d_out;

    cudaFuncSetAttribute(attn_tc,
                         cudaFuncAttributeMaxDynamicSharedMemorySize, ATTN_SMEM);

    qkv_tc<<<dim3(M / 128, H, 3), 256>>>(x, Wq, Wk, Wv);
    attn_tc<<<dim3(S / 128, B * H), 256, ATTN_SMEM>>>();
    proj_tc<<<dim3(M / 128, D / 16 / 4), 256>>>(x, Wo, bo);
    ln_kernel<<<M, 256>>>(gamma, beta, out);
}

// round 7
// speedup vs baseline: 8.1455x; 1.0456x over previous
#include <cuda_runtime.h>
#include <math.h>
#include <stdint.h>

#define B 4
#define S 2048
#define D 1024
#define H 16
#define DH 64
#define M (B * S)          // 8192
#define EPS 1e-5f

// ---------------- scratch (no allocations allowed) ----------------
__device__ uint32_t g_xh[(size_t)M * 512];          // X bf16 pairs [m][dp]
__device__ uint32_t g_wp[(size_t)H * 512 * 192];    // QKV weights packed [h][kp][z*64+dh]
__device__ uint32_t g_wop[(size_t)512 * 1024];      // Wo packed [kp][n]
__device__ uint32_t g_qh[(size_t)B * H * S * 32];   // Q bf16 pairs [bh][s][dhp], pre-scaled 0.125
__device__ uint32_t g_kt[(size_t)B * H * 32 * S];   // K bf16 pairs TRANSPOSED [bh][dhp][s]
__device__ uint32_t g_vh[(size_t)B * H * S * 32];   // V bf16 pairs [bh][s][dhp]
__device__ uint32_t g_cth[(size_t)M * 512];         // ctx bf16 pairs [m][dp] (concat heads)
__device__ float    g_tmp[(size_t)B * S * D];       // proj + residual, pre-LN (fp32)

// ---------------- helpers ----------------
__device__ __forceinline__ uint32_t f2bf2(float lo, float hi) {
    uint32_t d;
    asm("cvt.rn.bf16x2.f32 %0, %1, %2;" : "=r"(d) : "f"(hi), "f"(lo));
    return d;
}
__device__ __forceinline__ uint32_t prmt(uint32_t a, uint32_t b, uint32_t s) {
    uint32_t d;
    asm("prmt.b32 %0, %1, %2, %3;" : "=r"(d) : "r"(a), "r"(b), "r"(s));
    return d;
}
// D = A(16x16,row) * B(16x8,col) + D, bf16 in, f32 accum
__device__ __forceinline__ void mma16(float4& c, const uint32_t a[4],
                                      uint32_t b0, uint32_t b1) {
    asm volatile(
        "mma.sync.aligned.m16n8k16.row.col.f32.bf16.bf16.f32 "
        "{%0,%1,%2,%3}, {%4,%5,%6,%7}, {%8,%9}, {%0,%1,%2,%3};"
        : "+f"(c.x), "+f"(c.y), "+f"(c.z), "+f"(c.w)
        : "r"(a[0]), "r"(a[1]), "r"(a[2]), "r"(a[3]), "r"(b0), "r"(b1));
}

// ============================================================================
// Prologue: pack fp32 inputs into bf16-pair layouts.
// ============================================================================
__global__ __launch_bounds__(256) void cvt_x_kernel(const float* __restrict__ x)
{
    int idx = blockIdx.x * 256 + threadIdx.x;       // over M*512
    float2 v = *(const float2*)&x[(size_t)idx * 2];
    g_xh[idx] = f2bf2(v.x, v.y);
}

__global__ __launch_bounds__(256) void cvt_wqkv_kernel(
    const float* __restrict__ Wq,
    const float* __restrict__ Wk,
    const float* __restrict__ Wv)
{
    int idx = blockIdx.x * 256 + threadIdx.x;       // over H*512*192
    int n  = idx % 192;
    int kp = (idx / 192) & 511;
    int h  = idx / (192 * 512);
    int z = n >> 6, dh = n & 63;
    const float* W = (z == 0) ? Wq : (z == 1) ? Wk : Wv;
    size_t base = ((size_t)h * D + 2 * kp) * DH + dh;
    g_wp[idx] = f2bf2(W[base], W[base + DH]);
}

__global__ __launch_bounds__(256) void cvt_wo_kernel(const float* __restrict__ Wo)
{
    int idx = blockIdx.x * 256 + threadIdx.x;       // over 512*1024
    int n = idx & 1023;
    int kp = idx >> 10;
    g_wop[idx] = f2bf2(Wo[(size_t)(2 * kp) * 1024 + n],
                       Wo[(size_t)(2 * kp + 1) * 1024 + n]);
}

// ============================================================================
// Kernel 1: QKV projection, z-folded (bf16 MMA). grid (M/128, H), block 512.
// C tile 128x192 (N = z*64+dh), 16 warps 4m x 4n, warp tile 32x48.
// ============================================================================
#define XSB 20
#define WPB 200

__global__ __launch_bounds__(512) void qkv_tc()
{
    __shared__ __align__(16) uint32_t Xs[128 * XSB];
    __shared__ __align__(16) uint32_t Wp[16 * WPB];

    const int m0 = blockIdx.x * 128;
    const int h  = blockIdx.y;

    const int tid = threadIdx.x;
    const int w = tid >> 5, lane = tid & 31;
    const int g = lane >> 2, tq = lane & 3;
    const int wm = w >> 2, wn = w & 3;

    const int xr_r = tid >> 2, xr_c = (tid & 3) * 4;
    const int wrow = tid >> 5, wcol = tid & 31;

    uint4 xr;
    uint32_t wr[6];
    auto ldA = [&](int kp0) {
        xr = *(const uint4*)&g_xh[(size_t)(m0 + xr_r) * 512 + kp0 + xr_c];
        #pragma unroll
        for (int j = 0; j < 6; j++)
            wr[j] = g_wp[((size_t)h * 512 + kp0 + wrow) * 192 + wcol + 32 * j];
    };
    auto stA = [&]() {
        *(uint4*)&Xs[xr_r * XSB + xr_c] = xr;
        #pragma unroll
        for (int j = 0; j < 6; j++) Wp[wrow * WPB + wcol + 32 * j] = wr[j];
    };

    float4 acc[2][6];
    #pragma unroll
    for (int i = 0; i < 2; i++)
        #pragma unroll
        for (int j = 0; j < 6; j++) acc[i][j] = make_float4(0.f, 0.f, 0.f, 0.f);

    ldA(0); stA();
    __syncthreads();

    for (int kp0 = 0; kp0 < 512; kp0 += 16) {
        const bool nxt = (kp0 + 16 < 512);
        if (nxt) ldA(kp0 + 16);
        #pragma unroll
        for (int ks = 0; ks < 2; ks++) {
            const int kk = ks * 8;
            uint32_t a[2][4];
            #pragma unroll
            for (int mt = 0; mt < 2; mt++) {
                int rm = wm * 32 + mt * 16;
                a[mt][0] = Xs[(rm + g) * XSB + kk + tq];
                a[mt][1] = Xs[(rm + g + 8) * XSB + kk + tq];
                a[mt][2] = Xs[(rm + g) * XSB + kk + 4 + tq];
                a[mt][3] = Xs[(rm + g + 8) * XSB + kk + 4 + tq];
            }
            #pragma unroll
            for (int nt = 0; nt < 6; nt++) {
                int nb = wn * 48 + nt * 8;
                uint32_t b0 = Wp[(kk + tq) * WPB + nb + g];
                uint32_t b1 = Wp[(kk + 4 + tq) * WPB + nb + g];
                mma16(acc[0][nt], a[0], b0, b1);
                mma16(acc[1][nt], a[1], b0, b1);
            }
        }
        __syncthreads();
        if (nxt) { stA(); __syncthreads(); }
    }

    // epilogue: pack bf16 pairs, route by z
    const int bb = m0 >> 11;
    #pragma unroll
    for (int mt = 0; mt < 2; mt++) {
        int mrow = m0 + wm * 32 + mt * 16 + g;
        int s = mrow & (S - 1);
        #pragma unroll
        for (int nt = 0; nt < 6; nt++) {
            int n = wn * 48 + nt * 8 + 2 * tq;
            int z = n >> 6, dhp = (n & 63) >> 1;
            float sc = (z == 0) ? 0.125f : 1.0f;
            uint32_t u0 = f2bf2(acc[mt][nt].x * sc, acc[mt][nt].y * sc);
            uint32_t u1 = f2bf2(acc[mt][nt].z * sc, acc[mt][nt].w * sc);
            if (z == 1) {
                size_t base = ((size_t)(bb * H + h) * 32 + dhp) * S;
                g_kt[base + s]     = u0;
                g_kt[base + s + 8] = u1;
            } else {
                uint32_t* outp = (z == 0) ? g_qh : g_vh;
                size_t base = ((size_t)(bb * H + h) * S + s) * 32 + dhp;
                outp[base]          = u0;
                outp[base + 8 * 32] = u1;
            }
        }
    }
}

// ============================================================================
// Kernel 2: flash attention (bf16 MMA). grid (S/128, B*H), block 256.
// ============================================================================
#define QSB 36
#define KPB 72
#define VPB 72
#define PSB 36
#define ATTN_SMEM ((128 * QSB + 32 * KPB + 32 * VPB + 128 * PSB) * 4)

__global__ __launch_bounds__(256, 2) void attn_tc()
{
    extern __shared__ __align__(16) uint32_t sm[];
    uint32_t* Qs = sm;                      // [128][QSB]
    uint32_t* Kp = Qs + 128 * QSB;          // [32][KPB]
    uint32_t* Vp = Kp + 32 * KPB;           // [32][VPB]
    uint32_t* Ps = Vp + 32 * VPB;           // [128][PSB]

    const int bh = blockIdx.y;
    const int q0 = blockIdx.x * 128;
    const uint32_t* Qg = g_qh + (size_t)bh * S * 32;
    const uint32_t* Kt = g_kt + (size_t)bh * 32 * S;
    const uint32_t* Vh = g_vh + (size_t)bh * S * 32;

    const int tid = threadIdx.x;
    const int w = tid >> 5, lane = tid & 31;
    const int g = lane >> 2, tq = lane & 3;
    const int wq = w * 16;

    // ---- stage Q (straight copy of bf16 pairs, already scaled) ----
    {
        const int r = tid >> 3, c = (tid & 7) * 4;
        #pragma unroll
        for (int i = 0; i < 4; i++) {
            uint4 v = *(const uint4*)&Qg[(size_t)(q0 + r + 32 * i) * 32 + c];
            *(uint4*)&Qs[(r + 32 * i) * QSB + c] = v;
        }
    }

    uint4 kr[2];
    uint32_t va[4], vb[4];
    const int k_dhp = tid >> 4, k_c = (tid & 15) * 4;
    const int v_dhp = tid & 31;

    auto ldKV = [&](int kt) {
        #pragma unroll
        for (int i = 0; i < 2; i++)
            kr[i] = *(const uint4*)&Kt[(size_t)(k_dhp + 16 * i) * S + kt + k_c];
        #pragma unroll
        for (int i = 0; i < 4; i++) {
            int sp = (tid >> 5) + 8 * i;
            va[i] = Vh[(size_t)(kt + 2 * sp) * 32 + v_dhp];
            vb[i] = Vh[(size_t)(kt + 2 * sp + 1) * 32 + v_dhp];
        }
    };
    auto stKV = [&]() {
        #pragma unroll
        for (int i = 0; i < 2; i++)
            *(uint4*)&Kp[(k_dhp + 16 * i) * KPB + k_c] = kr[i];
        #pragma unroll
        for (int i = 0; i < 4; i++) {
            int sp = (tid >> 5) + 8 * i;
            *(uint2*)&Vp[sp * VPB + 2 * v_dhp] =
                make_uint2(prmt(va[i], vb[i], 0x5410), prmt(va[i], vb[i], 0x7632));
        }
    };

    float m_run[2] = { -1e30f, -1e30f };
    float l_run[2] = { 0.f, 0.f };
    float4 oacc[8];
    #pragma unroll
    for (int i = 0; i < 8; i++) oacc[i] = make_float4(0.f, 0.f, 0.f, 0.f);

    ldKV(0);
    stKV();
    __syncthreads();

    for (int kt = 0; kt < S; kt += 64) {
        const bool nxt = (kt + 64 < S);
        if (nxt) ldKV(kt + 64);

        // ---- scores S = Q @ K^T ----
        float4 sacc[8];
        #pragma unroll
        for (int i = 0; i < 8; i++) sacc[i] = make_float4(0.f, 0.f, 0.f, 0.f);

        #pragma unroll
        for (int ks = 0; ks < 4; ks++) {
            const int kp0 = ks * 8;
            uint32_t a[4];
            a[0] = Qs[(wq + g) * QSB + kp0 + tq];
            a[1] = Qs[(wq + g + 8) * QSB + kp0 + tq];
            a[2] = Qs[(wq + g) * QSB + kp0 + 4 + tq];
            a[3] = Qs[(wq + g + 8) * QSB + kp0 + 4 + tq];
            #pragma unroll
            for (int nt = 0; nt < 8; nt++) {
                uint32_t b0 = Kp[(kp0 + tq) * KPB + nt * 8 + g];
                uint32_t b1 = Kp[(kp0 + 4 + tq) * KPB + nt * 8 + g];
                mma16(sacc[nt], a, b0, b1);
            }
        }

        // ---- online softmax ----
        float tm0 = -1e30f, tm1 = -1e30f;
        #pragma unroll
        for (int nt = 0; nt < 8; nt++) {
            tm0 = fmaxf(tm0, fmaxf(sacc[nt].x, sacc[nt].y));
            tm1 = fmaxf(tm1, fmaxf(sacc[nt].z, sacc[nt].w));
        }
        tm0 = fmaxf(tm0, __shfl_xor_sync(0xffffffffu, tm0, 1));
        tm0 = fmaxf(tm0, __shfl_xor_sync(0xffffffffu, tm0, 2));
        tm1 = fmaxf(tm1, __shfl_xor_sync(0xffffffffu, tm1, 1));
        tm1 = fmaxf(tm1, __shfl_xor_sync(0xffffffffu, tm1, 2));

        float mn0 = fmaxf(m_run[0], tm0);
        float mn1 = fmaxf(m_run[1], tm1);
        float al0 = __expf(m_run[0] - mn0);
        float al1 = __expf(m_run[1] - mn1);
        m_run[0] = mn0; m_run[1] = mn1;

        float rs0 = 0.f, rs1 = 0.f;
        #pragma unroll
        for (int nt = 0; nt < 8; nt++) {
            float p0 = __expf(sacc[nt].x - mn0);
            float p1 = __expf(sacc[nt].y - mn0);
            float p2 = __expf(sacc[nt].z - mn1);
            float p3 = __expf(sacc[nt].w - mn1);
            rs0 += p0 + p1; rs1 += p2 + p3;
            Ps[(wq + g) * PSB + nt * 4 + tq]     = f2bf2(p0, p1);
            Ps[(wq + g + 8) * PSB + nt * 4 + tq] = f2bf2(p2, p3);
        }
        rs0 += __shfl_xor_sync(0xffffffffu, rs0, 1);
        rs0 += __shfl_xor_sync(0xffffffffu, rs0, 2);
        rs1 += __shfl_xor_sync(0xffffffffu, rs1, 1);
        rs1 += __shfl_xor_sync(0xffffffffu, rs1, 2);
        l_run[0] = l_run[0] * al0 + rs0;
        l_run[1] = l_run[1] * al1 + rs1;
        #pragma unroll
        for (int nt = 0; nt < 8; nt++) {
            oacc[nt].x *= al0; oacc[nt].y *= al0;
            oacc[nt].z *= al1; oacc[nt].w *= al1;
        }
        __syncwarp();

        // ---- PV ----
        #pragma unroll
        for (int ks = 0; ks < 4; ks++) {
            const int kp0 = ks * 8;
            uint32_t a[4];
            a[0] = Ps[(wq + g) * PSB + kp0 + tq];
            a[1] = Ps[(wq + g + 8) * PSB + kp0 + tq];
            a[2] = Ps[(wq + g) * PSB + kp0 + 4 + tq];
            a[3] = Ps[(wq + g + 8) * PSB + kp0 + 4 + tq];
            #pragma unroll
            for (int nt = 0; nt < 8; nt++) {
                uint32_t b0 = Vp[(kp0 + tq) * VPB + nt * 8 + g];
                uint32_t b1 = Vp[(kp0 + 4 + tq) * VPB + nt * 8 + g];
                mma16(oacc[nt], a, b0, b1);
            }
        }
        __syncthreads();
        if (nxt) { stKV(); __syncthreads(); }
    }

    // ---- epilogue: normalize, write ctx as bf16 pairs [m][dp] ----
    const int bb = bh >> 4, h = bh & 15;
    const float inv0 = 1.f / l_run[0];
    const float inv1 = 1.f / l_run[1];
    const int r0 = q0 + wq + g;
    size_t base0 = (size_t)(bb * S + r0) * 512 + h * 32;
    size_t base1 = (size_t)(bb * S + r0 + 8) * 512 + h * 32;
    #pragma unroll
    for (int nt = 0; nt < 8; nt++) {
        int dhp = nt * 4 + tq;
        g_cth[base0 + dhp] = f2bf2(oacc[nt].x * inv0, oacc[nt].y * inv0);
        g_cth[base1 + dhp] = f2bf2(oacc[nt].z * inv1, oacc[nt].w * inv1);
    }
}

// ============================================================================
// Kernel 3: output projection + bias + residual (bf16 MMA).
// grid (M/128, D/128), block 256, 8 warps 2m x 4n, warp tile 64x32.
// ============================================================================
#define PXB 20
#define POB 136

__global__ __launch_bounds__(256) void proj_tc(
    const float* __restrict__ x,
    const float* __restrict__ bo)
{
    __shared__ __align__(16) uint32_t Xs[128 * PXB];
    __shared__ __align__(16) uint32_t Wp[16 * POB];

    const int m0 = blockIdx.x * 128;
    const int n0 = blockIdx.y * 128;

    const int tid = threadIdx.x;
    const int w = tid >> 5, lane = tid & 31;
    const int g = lane >> 2, tq = lane & 3;
    const int wm = w >> 2, wn = w & 3;

    uint4 xr[2];
    uint32_t wr[8];
    auto ldA = [&](int kp0) {
        #pragma unroll
        for (int i = 0; i < 2; i++) {
            int idx = tid + 256 * i;
            xr[i] = *(const uint4*)&g_cth[(size_t)(m0 + (idx >> 2)) * 512 + kp0 + (idx & 3) * 4];
        }
        #pragma unroll
        for (int j = 0; j < 8; j++)
            wr[j] = g_wop[(size_t)(kp0 + (tid >> 4)) * 1024 + n0 + (tid & 15) + 16 * j];
    };
    auto stA = [&]() {
        #pragma unroll
        for (int i = 0; i < 2; i++) {
            int idx = tid + 256 * i;
            *(uint4*)&Xs[(idx >> 2) * PXB + (idx & 3) * 4] = xr[i];
        }
        #pragma unroll
        for (int j = 0; j < 8; j++)
            Wp[(tid >> 4) * POB + (tid & 15) + 16 * j] = wr[j];
    };

    float4 acc[4][4];
    #pragma unroll
    for (int i = 0; i < 4; i++)
        #pragma unroll
        for (int j = 0; j < 4; j++) acc[i][j] = make_float4(0.f, 0.f, 0.f, 0.f);

    ldA(0); stA();
    __syncthreads();

    for (int kp0 = 0; kp0 < 512; kp0 += 16) {
        const bool nxt = (kp0 + 16 < 512);
        if (nxt) ldA(kp0 + 16);
        #pragma unroll
        for (int ks = 0; ks < 2; ks++) {
            const int kk = ks * 8;
            uint32_t a[4][4];
            #pragma unroll
            for (int mt = 0; mt < 4; mt++) {
                int rm = wm * 64 + mt * 16;
                a[mt][0] = Xs[(rm + g) * PXB + kk + tq];
                a[mt][1] = Xs[(rm + g + 8) * PXB + kk + tq];
                a[mt][2] = Xs[(rm + g) * PXB + kk + 4 + tq];
                a[mt][3] = Xs[(rm + g + 8) * PXB + kk + 4 + tq];
            }
            #pragma unroll
            for (int nt = 0; nt < 4; nt++) {
                int nb = wn * 32 + nt * 8;
                uint32_t b0 = Wp[(kk + tq) * POB + nb + g];
                uint32_t b1 = Wp[(kk + 4 + tq) * POB + nb + g];
                #pragma unroll
                for (int mt = 0; mt < 4; mt++) mma16(acc[mt][nt], a[mt], b0, b1);
            }
        }
        __syncthreads();
        if (nxt) { stA(); __syncthreads(); }
    }

    #pragma unroll
    for (int mt = 0; mt < 4; mt++) {
        int m = m0 + wm * 64 + mt * 16 + g;
        #pragma unroll
        for (int nt = 0; nt < 4; nt++) {
            int col = n0 + wn * 32 + nt * 8 + 2 * tq;
            float2 b2 = *(const float2*)&bo[col];
            float2 x0 = *(const float2*)&x[(size_t)m * D + col];
            float2 x1 = *(const float2*)&x[(size_t)(m + 8) * D + col];
            *(float2*)&g_tmp[(size_t)m * D + col] =
                make_float2(acc[mt][nt].x + b2.x + x0.x, acc[mt][nt].y + b2.y + x0.y);
            *(float2*)&g_tmp[(size_t)(m + 8) * D + col] =
                make_float2(acc[mt][nt].z + b2.x + x1.x, acc[mt][nt].w + b2.y + x1.y);
        }
    }
}

// ============================================================================
// Kernel 4: LayerNorm per row.  grid M, block 256 (4 floats / thread).
// ============================================================================
__global__ __launch_bounds__(256) void ln_kernel(
    const float* __restrict__ gamma,
    const float* __restrict__ beta,
    float* __restrict__ out)
{
    const int row = blockIdx.x;
    const int t = threadIdx.x;
    const float4* src = (const float4*)(g_tmp + (size_t)row * D);
    float4 v = src[t];

    float s = v.x + v.y + v.z + v.w;
    float q = v.x * v.x + v.y * v.y + v.z * v.z + v.w * v.w;
    #pragma unroll
    for (int o = 16; o > 0; o >>= 1) {
        s += __shfl_xor_sync(0xffffffffu, s, o);
        q += __shfl_xor_sync(0xffffffffu, q, o);
    }
    __shared__ float sh[16];
    int w = t >> 5, lane = t & 31;
    if (lane == 0) { sh[w] = s; sh[8 + w] = q; }
    __syncthreads();
    if (t < 32) {
        s = (lane < 8) ? sh[lane] : 0.f;
        q = (lane < 8) ? sh[8 + lane] : 0.f;
        #pragma unroll
        for (int o = 4; o > 0; o >>= 1) {
            s += __shfl_xor_sync(0xffffffffu, s, o);
            q += __shfl_xor_sync(0xffffffffu, q, o);
        }
        if (lane == 0) { sh[0] = s; sh[1] = q; }
    }
    __syncthreads();
    float mu  = sh[0] * (1.f / D);
    float var = sh[1] * (1.f / D) - mu * mu;
    float rstd = rsqrtf(var + EPS);

    float4 g = ((const float4*)gamma)[t];
    float4 bb = ((const float4*)beta)[t];
    float4 o4;
    o4.x = (v.x - mu) * rstd * g.x + bb.x;
    o4.y = (v.y - mu) * rstd * g.y + bb.y;
    o4.z = (v.z - mu) * rstd * g.z + bb.z;
    o4.w = (v.w - mu) * rstd * g.w + bb.w;
    ((float4*)(out + (size_t)row * D))[t] = o4;
}

// ============================================================================
// launcher
// ============================================================================
extern "C" void kernel_launch(void* const* d_in, const int* in_sizes, int n_in,
                              void* d_out, int out_size)
{
    const float* x     = (const float*)d_in[0];
    const float* Wq    = (const float*)d_in[1];
    const float* Wk    = (const float*)d_in[2];
    const float* Wv    = (const float*)d_in[3];
    const float* Wo    = (const float*)d_in[4];
    const float* bo    = (const float*)d_in[5];
    const float* gamma = (const float*)d_in[6];
    const float* beta  = (const float*)d_in[7];
    float* out = (float*)d_out;

    cudaFuncSetAttribute(attn_tc,
                         cudaFuncAttributeMaxDynamicSharedMemorySize, ATTN_SMEM);

    cvt_x_kernel<<<(M * 512) / 256, 256>>>(x);
    cvt_wqkv_kernel<<<(H * 512 * 192) / 256, 256>>>(Wq, Wk, Wv);
    cvt_wo_kernel<<<(512 * 1024) / 256, 256>>>(Wo);
    qkv_tc<<<dim3(M / 128, H), 512>>>();
    attn_tc<<<dim3(S / 128, B * H), 256, ATTN_SMEM>>>();
    proj_tc<<<dim3(M / 128, D / 128), 256>>>(x, bo);
    ln_kernel<<<M, 256>>>(gamma, beta, out);
}